// round 15
// baseline (speedup 1.0000x reference)
#include <cuda_runtime.h>
#include <cuda_fp16.h>
#include <cstdint>

#define N_USERS 100000
#define N_ITEMS 150000
#define N_NODES (N_USERS + N_ITEMS)
#define N_EDGES 4000000
#define DIM 64

#define SCAN_TB   256
#define SCAN_IPT  4
#define SCAN_TILE (SCAN_TB * SCAN_IPT)                    // 1024
#define N_SCAN_BLOCKS ((N_NODES + SCAN_TILE - 1) / SCAN_TILE)  // 245

#define G_CVT ((N_NODES * DIM / 2) / SCAN_TB)             // 31250 convert blocks
#define G_E4  ((N_EDGES / 4 + SCAN_TB - 1) / SCAN_TB)     // 3907 hist blocks

// fp16 embeddings: x0 = quantized inputs, x1/x2 = layer outputs (32 MB each)
__device__ __half g_x0[(size_t)N_NODES * DIM];
__device__ __half g_x1[(size_t)N_NODES * DIM];
__device__ __half g_x2[(size_t)N_NODES * DIM];
// CSR machinery (g_cnt zero-init at load; scan_lookback re-zeroes it each
// launch after consuming it; g_tstate re-zeroed by convert_hist each launch)
__device__ int      g_cnt[N_NODES];
__device__ int      g_rp[N_NODES + 1];
__device__ int      g_offs[N_NODES];
__device__ unsigned g_tstate[N_SCAN_BLOCKS];   // (flag<<30)|value, flag:1=agg,2=inc
__device__ int2     g_edges[N_EDGES];          // {src_byte_off, w_half2}, dst-sorted

// ---------- k0: convert fp32->fp16 AND histogram AND tstate init ----------
__global__ void convert_hist(const float* __restrict__ user_emb,
                             const float* __restrict__ item_emb,
                             __half* __restrict__ x0,
                             const int* __restrict__ edst,
                             int* __restrict__ cnt) {
    int bid = blockIdx.x, tid = threadIdx.x;
    if (bid == 0 && tid < N_SCAN_BLOCKS) g_tstate[tid] = 0;
    if (bid < G_CVT) {
        size_t i = (size_t)bid * SCAN_TB + tid;            // half2 index
        const size_t ub2 = (size_t)N_USERS * DIM / 2;
        float2 v;
        if (i < ub2) v = __ldcs(((const float2*)user_emb) + i);
        else         v = __ldcs(((const float2*)item_emb) + (i - ub2));
        ((__half2*)x0)[i] = __float22half2_rn(v);
    } else {
        int i = (bid - G_CVT) * SCAN_TB + tid;             // edge/4 index
        if (i < N_EDGES / 4) {
            int4 d = __ldcs(((const int4*)edst) + i);
            atomicAdd(cnt + d.x, 1);
            atomicAdd(cnt + d.y, 1);
            atomicAdd(cnt + d.z, 1);
            atomicAdd(cnt + d.w, 1);
        }
    }
}

// ---------- k1: single-pass exclusive scan (decoupled lookback) ----------
__global__ void __launch_bounds__(SCAN_TB) scan_lookback(
    int* __restrict__ cnt, int* __restrict__ rp, int* __restrict__ offs) {
    __shared__ int wsum[8];
    __shared__ int s_prefix;
    int b   = blockIdx.x;
    int tid = threadIdx.x;
    int base = b * SCAN_TILE + tid * SCAN_IPT;

    int v0 = 0, v1 = 0, v2 = 0, v3 = 0;
    if (base + 3 < N_NODES) {
        int4 t = *(const int4*)(cnt + base);
        v0 = t.x; v1 = t.y; v2 = t.z; v3 = t.w;
        *(int4*)(cnt + base) = make_int4(0, 0, 0, 0);      // reset invariant
    } else {
        if (base     < N_NODES) { v0 = cnt[base];     cnt[base]     = 0; }
        if (base + 1 < N_NODES) { v1 = cnt[base + 1]; cnt[base + 1] = 0; }
        if (base + 2 < N_NODES) { v2 = cnt[base + 2]; cnt[base + 2] = 0; }
        if (base + 3 < N_NODES) { v3 = cnt[base + 3]; cnt[base + 3] = 0; }
    }
    int tsum = v0 + v1 + v2 + v3;
    int lane = tid & 31, wid = tid >> 5;
    int inc = tsum;
    #pragma unroll
    for (int o = 1; o < 32; o <<= 1) {
        int t = __shfl_up_sync(0xffffffffu, inc, o);
        if (lane >= o) inc += t;
    }
    if (lane == 31) wsum[wid] = inc;
    __syncthreads();
    if (tid < 8) {
        int w = wsum[tid];
        #pragma unroll
        for (int o = 1; o < 8; o <<= 1) {
            int t = __shfl_up_sync(0xffu, w, o);
            if (tid >= o) w += t;
        }
        wsum[tid] = w;
    }
    __syncthreads();
    int excl  = inc - tsum + (wid ? wsum[wid - 1] : 0);
    int total = wsum[7];

    if (tid == 0) {
        if (b == 0) atomicExch(&g_tstate[0], (2u << 30) | (unsigned)total);
        else        atomicExch(&g_tstate[b], (1u << 30) | (unsigned)total);
    }
    if (b == 0) {
        if (tid == 0) s_prefix = 0;
    } else if (tid < 32) {
        int idxb = b - 1;
        int prefix = 0;
        while (true) {
            int j = idxb - lane;
            unsigned st = (j >= 0) ? atomicAdd(&g_tstate[j], 0u) : (2u << 30);
            unsigned flag = st >> 30;
            if (__all_sync(0xffffffffu, flag != 0u)) {
                unsigned incmask = __ballot_sync(0xffffffffu, flag == 2u);
                int firstinc = incmask ? (__ffs(incmask) - 1) : 32;
                int contrib = (lane <= firstinc) ? (int)(st & 0x3FFFFFFFu) : 0;
                #pragma unroll
                for (int o = 16; o > 0; o >>= 1)
                    contrib += __shfl_down_sync(0xffffffffu, contrib, o);
                contrib = __shfl_sync(0xffffffffu, contrib, 0);
                prefix += contrib;
                if (firstinc < 32) break;
                idxb -= 32;
            }
        }
        if (lane == 0) {
            atomicExch(&g_tstate[b], (2u << 30) | (unsigned)(prefix + total));
            s_prefix = prefix;
        }
    }
    __syncthreads();
    int p = s_prefix;
    if (base     < N_NODES) { int v = excl + p;                rp[base]     = v; offs[base]     = v; }
    if (base + 1 < N_NODES) { int v = excl + v0 + p;           rp[base + 1] = v; offs[base + 1] = v; }
    if (base + 2 < N_NODES) { int v = excl + v0 + v1 + p;      rp[base + 2] = v; offs[base + 2] = v; }
    if (base + 3 < N_NODES) { int v = excl + v0 + v1 + v2 + p; rp[base + 3] = v; offs[base + 3] = v; }
    if (b == 0 && tid == 0) rp[N_NODES] = N_EDGES;
}

// ---------- k2: scatter edges into dst-sorted packed array ----------
// Descriptor = {src byte offset (src*128), weight pre-packed as half2}.
__global__ void scatter_kernel(const int* __restrict__ esrc,
                               const int* __restrict__ edst,
                               const float* __restrict__ ev,
                               int* __restrict__ offs,
                               int2* __restrict__ edges) {
    int i = blockIdx.x * blockDim.x + threadIdx.x;         // edge/4 index
    if (i >= N_EDGES / 4) return;
    int4   s = __ldcs(((const int4*)esrc) + i);
    int4   d = __ldcs(((const int4*)edst) + i);
    float4 w = __ldcs(((const float4*)ev) + i);
    int p0 = atomicAdd(offs + d.x, 1);
    int p1 = atomicAdd(offs + d.y, 1);
    int p2 = atomicAdd(offs + d.z, 1);
    int p3 = atomicAdd(offs + d.w, 1);
    __half2 h0 = __float2half2_rn(w.x);
    __half2 h1 = __float2half2_rn(w.y);
    __half2 h2 = __float2half2_rn(w.z);
    __half2 h3 = __float2half2_rn(w.w);
    edges[p0] = make_int2(s.x << 7, *(int*)&h0);
    edges[p1] = make_int2(s.y << 7, *(int*)&h1);
    edges[p2] = make_int2(s.z << 7, *(int*)&h2);
    edges[p3] = make_int2(s.w << 7, *(int*)&h3);
}

// ---------- k3..k5: gather-only SpMM ----------
// Warp/node, smem staging, MLP=8. Per edge: LDS descriptor, 1 add (byte
// offset precomputed), LDG.32, ONE HFMA2 (fp16 accumulate, 4 chains).
// fp16 chains flushed to fp32 after every <=32-edge chunk.
template<int FUSE>
__global__ void __launch_bounds__(256) spmm_f16(
    const int2*   __restrict__ edges,
    const int*    __restrict__ rp,
    const __half* __restrict__ x,
    __half*       __restrict__ y,      // !FUSE
    const float*  __restrict__ f_u,    // FUSE: user_emb
    const float*  __restrict__ f_i,    // FUSE: item_emb
    const __half* __restrict__ f_x1,   // FUSE
    const __half* __restrict__ f_x2,   // FUSE
    float*        __restrict__ fout)   // FUSE
{
    __shared__ int2 s_edges[8][32];
    int wib  = threadIdx.x >> 5;
    int node = (int)((blockIdx.x * blockDim.x + threadIdx.x) >> 5);
    int lane = threadIdx.x & 31;
    if (node >= N_NODES) return;

    int e   = __ldg(rp + node);
    int end = __ldg(rp + node + 1);

    const char* xl = ((const char*)x) + lane * 4;  // hoisted lane base

    float a0x = 0.f, a0y = 0.f, a1x = 0.f, a1y = 0.f;
    float a2x = 0.f, a2y = 0.f, a3x = 0.f, a3y = 0.f;

    while (e < end) {
        int n = end - e; if (n > 32) n = 32;
        if (lane < n) s_edges[wib][lane] = __ldg(edges + e + lane);
        __syncwarp();

        __half2 h0 = __float2half2_rn(0.f);
        __half2 h1 = h0, h2 = h0, h3 = h0;

        int k = 0;
        for (; k + 7 < n; k += 8) {
            int2 p0 = s_edges[wib][k];
            int2 p1 = s_edges[wib][k + 1];
            int2 p2 = s_edges[wib][k + 2];
            int2 p3 = s_edges[wib][k + 3];
            int2 p4 = s_edges[wib][k + 4];
            int2 p5 = s_edges[wib][k + 5];
            int2 p6 = s_edges[wib][k + 6];
            int2 p7 = s_edges[wib][k + 7];
            unsigned g0 = __ldcg((const unsigned*)(xl + p0.x));
            unsigned g1 = __ldcg((const unsigned*)(xl + p1.x));
            unsigned g2 = __ldcg((const unsigned*)(xl + p2.x));
            unsigned g3 = __ldcg((const unsigned*)(xl + p3.x));
            unsigned g4 = __ldcg((const unsigned*)(xl + p4.x));
            unsigned g5 = __ldcg((const unsigned*)(xl + p5.x));
            unsigned g6 = __ldcg((const unsigned*)(xl + p6.x));
            unsigned g7 = __ldcg((const unsigned*)(xl + p7.x));
            h0 = __hfma2(*(__half2*)&p0.y, *(__half2*)&g0, h0);
            h1 = __hfma2(*(__half2*)&p1.y, *(__half2*)&g1, h1);
            h2 = __hfma2(*(__half2*)&p2.y, *(__half2*)&g2, h2);
            h3 = __hfma2(*(__half2*)&p3.y, *(__half2*)&g3, h3);
            h0 = __hfma2(*(__half2*)&p4.y, *(__half2*)&g4, h0);
            h1 = __hfma2(*(__half2*)&p5.y, *(__half2*)&g5, h1);
            h2 = __hfma2(*(__half2*)&p6.y, *(__half2*)&g6, h2);
            h3 = __hfma2(*(__half2*)&p7.y, *(__half2*)&g7, h3);
        }
        for (; k + 3 < n; k += 4) {
            int2 p0 = s_edges[wib][k];
            int2 p1 = s_edges[wib][k + 1];
            int2 p2 = s_edges[wib][k + 2];
            int2 p3 = s_edges[wib][k + 3];
            unsigned g0 = __ldcg((const unsigned*)(xl + p0.x));
            unsigned g1 = __ldcg((const unsigned*)(xl + p1.x));
            unsigned g2 = __ldcg((const unsigned*)(xl + p2.x));
            unsigned g3 = __ldcg((const unsigned*)(xl + p3.x));
            h0 = __hfma2(*(__half2*)&p0.y, *(__half2*)&g0, h0);
            h1 = __hfma2(*(__half2*)&p1.y, *(__half2*)&g1, h1);
            h2 = __hfma2(*(__half2*)&p2.y, *(__half2*)&g2, h2);
            h3 = __hfma2(*(__half2*)&p3.y, *(__half2*)&g3, h3);
        }
        for (; k < n; ++k) {
            int2 p = s_edges[wib][k];
            unsigned g = __ldcg((const unsigned*)(xl + p.x));
            h0 = __hfma2(*(__half2*)&p.y, *(__half2*)&g, h0);
        }
        // flush fp16 chains -> fp32 (once per <=32-edge chunk)
        float2 f0 = __half22float2(h0);
        float2 f1 = __half22float2(h1);
        float2 f2 = __half22float2(h2);
        float2 f3 = __half22float2(h3);
        a0x += f0.x; a0y += f0.y; a1x += f1.x; a1y += f1.y;
        a2x += f2.x; a2y += f2.y; a3x += f3.x; a3y += f3.y;

        __syncwarp();
        e += n;
    }

    float ox = (a0x + a1x) + (a2x + a3x);
    float oy = (a0y + a1y) + (a2y + a3y);

    const size_t ro = (size_t)node * DIM + (size_t)lane * 2;
    if (FUSE) {
        float2 e0;
        if (node < N_USERS) e0 = __ldcs((const float2*)(f_u + ro));
        else                e0 = __ldcs((const float2*)(f_i + ro - (size_t)N_USERS * DIM));
        float2 q1 = __half22float2(__ldcs(((const __half2*)f_x1) + (ro >> 1)));
        float2 q2 = __half22float2(__ldcs(((const __half2*)f_x2) + (ro >> 1)));
        float rx = (e0.x + q1.x + q2.x + ox) * 0.25f;
        float ry = (e0.y + q1.y + q2.y + oy) * 0.25f;
        float* p = fout + ro;
        asm volatile("st.global.cs.v2.f32 [%0], {%1, %2};"
                     :: "l"(p), "f"(rx), "f"(ry) : "memory");
    } else {
        __half2 h = __float22half2_rn(make_float2(ox, oy));
        unsigned hu = *reinterpret_cast<unsigned*>(&h);
        __half* p = y + ro;
        asm volatile("st.global.cs.b32 [%0], %1;"
                     :: "l"(p), "r"(hu) : "memory");
    }
}

extern "C" void kernel_launch(void* const* d_in, const int* in_sizes, int n_in,
                              void* d_out, int out_size) {
    const float* user_emb = (const float*)d_in[0];
    const float* item_emb = (const float*)d_in[1];
    const float* evals    = (const float*)d_in[2];
    const int*   esrc     = (const int*)  d_in[3];
    const int*   edst     = (const int*)  d_in[4];
    float* out = (float*)d_out;

    __half *x0, *x1, *x2; int *cnt, *rp, *offs; int2 *edges;
    cudaGetSymbolAddress((void**)&x0,    g_x0);
    cudaGetSymbolAddress((void**)&x1,    g_x1);
    cudaGetSymbolAddress((void**)&x2,    g_x2);
    cudaGetSymbolAddress((void**)&cnt,   g_cnt);
    cudaGetSymbolAddress((void**)&rp,    g_rp);
    cudaGetSymbolAddress((void**)&offs,  g_offs);
    cudaGetSymbolAddress((void**)&edges, g_edges);

    const int TB = 256;
    const int g_spmm = (int)(((size_t)N_NODES * 32 + TB - 1) / TB);

    convert_hist<<<G_CVT + G_E4, TB>>>(user_emb, item_emb, x0, edst, cnt);
    scan_lookback<<<N_SCAN_BLOCKS, SCAN_TB>>>(cnt, rp, offs);
    scatter_kernel<<<G_E4, TB>>>(esrc, edst, evals, offs, edges);

    spmm_f16<0><<<g_spmm, TB>>>(edges, rp, x0, x1,
                                nullptr, nullptr, nullptr, nullptr, nullptr);
    spmm_f16<0><<<g_spmm, TB>>>(edges, rp, x1, x2,
                                nullptr, nullptr, nullptr, nullptr, nullptr);
    spmm_f16<1><<<g_spmm, TB>>>(edges, rp, x2, nullptr,
                                user_emb, item_emb, x1, x2, out);
}